// round 6
// baseline (speedup 1.0000x reference)
#include <cuda_runtime.h>

typedef unsigned long long u64;

#define BATCH 32
#define NSEQ  2048
#define F     32
#define SPLITS 32
#define ROWS1 64                // rows per kernel-1 block
#define INV_N (1.0f / 2048.0f)

// Scratch (fully overwritten every launch -> deterministic)
__device__ float g_Mpart[BATCH * SPLITS * F * F];   // 16 MB
__device__ float g_M2[BATCH * F * F];               // (M @ w_r) * invN

// ---- packed f32x2 helpers ----
__device__ __forceinline__ u64 pk2(float a, float b) {
    u64 r; asm("mov.b64 %0,{%1,%2};" : "=l"(r) : "f"(a), "f"(b)); return r;
}
__device__ __forceinline__ float2 up2(u64 v) {
    float2 f; asm("mov.b64 {%0,%1},%2;" : "=f"(f.x), "=f"(f.y) : "l"(v)); return f;
}
__device__ __forceinline__ u64 ffma2(u64 a, u64 b, u64 c) {
    u64 d; asm("fma.rn.f32x2 %0,%1,%2,%3;" : "=l"(d) : "l"(a), "l"(b), "l"(c)); return d;
}
__device__ __forceinline__ u64 add2(u64 a, u64 b) {
    u64 d; asm("add.rn.f32x2 %0,%1,%2;" : "=l"(d) : "l"(a), "l"(b)); return d;
}

// ---------------------------------------------------------------------------
// Kernel 1: partial M_b[f1][f2] = sum_j phi[j][f1]*u[j][f2] over 64-row slice.
// 128 threads: phase A = 2 threads/row (16 features each, packed ffma2).
// ---------------------------------------------------------------------------
__global__ __launch_bounds__(128) void k_partialM(
    const float* __restrict__ x,
    const float* __restrict__ w_phi, const float* __restrict__ b_phi,
    const float* __restrict__ w_u,   const float* __restrict__ b_u)
{
    __shared__ alignas(16) float ws_phi[F * F], ws_u[F * F];
    __shared__ alignas(16) float bs_phi[F], bs_u[F];
    __shared__ alignas(16) float phi_s[ROWS1 * 34];   // [j][f], stride 34
    __shared__ alignas(16) float u_s[ROWS1 * 34];

    const int b     = blockIdx.x;
    const int split = blockIdx.y;
    const int t     = threadIdx.x;

#pragma unroll
    for (int i = t; i < 256; i += 128) {
        ((float4*)ws_phi)[i] = ((const float4*)w_phi)[i];
        ((float4*)ws_u  )[i] = ((const float4*)w_u  )[i];
    }
    if (t < F) { bs_phi[t] = b_phi[t]; bs_u[t] = b_u[t]; }
    __syncthreads();

    // ---- Phase A: row r = t&63, half h = t>>6 computes features [h*16, h*16+16)
    const int r    = t & 63;
    const int h    = t >> 6;
    const int hoff = h * 16;
    const int row  = split * ROWS1 + r;

    const float4* xr = (const float4*)(x + ((size_t)b * NSEQ + row) * F);
    float xv[F];
#pragma unroll
    for (int i = 0; i < 8; i++) {
        float4 v = xr[i];
        xv[4*i+0] = v.x; xv[4*i+1] = v.y; xv[4*i+2] = v.z; xv[4*i+3] = v.w;
    }

    u64 ph[8], uv[8];
#pragma unroll
    for (int i = 0; i < 8; i++) {
        ph[i] = ((const u64*)bs_phi)[h * 8 + i];
        uv[i] = ((const u64*)bs_u  )[h * 8 + i];
    }
#pragma unroll
    for (int k = 0; k < F; k++) {
        const u64 xk2 = pk2(xv[k], xv[k]);
        const ulonglong2* wp = (const ulonglong2*)(ws_phi + k * F + hoff);
        const ulonglong2* wu = (const ulonglong2*)(ws_u   + k * F + hoff);
#pragma unroll
        for (int q = 0; q < 4; q++) {
            ulonglong2 a = wp[q];
            ph[2*q+0] = ffma2(xk2, a.x, ph[2*q+0]);
            ph[2*q+1] = ffma2(xk2, a.y, ph[2*q+1]);
        }
#pragma unroll
        for (int q = 0; q < 4; q++) {
            ulonglong2 a = wu[q];
            uv[2*q+0] = ffma2(xk2, a.x, uv[2*q+0]);
            uv[2*q+1] = ffma2(xk2, a.y, uv[2*q+1]);
        }
    }
    u64* prow = (u64*)(phi_s + r * 34 + hoff);
    u64* urow = (u64*)(u_s   + r * 34 + hoff);
#pragma unroll
    for (int i = 0; i < 8; i++) {
        prow[i] = ph[i];
        float2 tu = up2(uv[i]);
        urow[i] = pk2(fmaxf(tu.x, 0.0f), fmaxf(tu.y, 0.0f));
    }
    __syncthreads();

    // ---- Phase B: warp w owns f1 in [8w,8w+8), lane = f2. Packed f1 pairs.
    const int lane = t & 31;
    const int w    = t >> 5;
    u64 acc2[4] = {0ull, 0ull, 0ull, 0ull};

#pragma unroll 4
    for (int j = 0; j < ROWS1; j++) {
        const float uj = u_s[j * 34 + lane];               // conflict-free
        const u64 uj2 = pk2(uj, uj);
        const u64* pr = (const u64*)(phi_s + j * 34 + w * 8);  // broadcast
#pragma unroll
        for (int q = 0; q < 4; q++)
            acc2[q] = ffma2(uj2, pr[q], acc2[q]);
    }

    float* mp = g_Mpart + ((size_t)(b * SPLITS + split)) * F * F;
#pragma unroll
    for (int q = 0; q < 4; q++) {
        float2 v = up2(acc2[q]);
        mp[(w * 8 + 2*q + 0) * F + lane] = v.x;
        mp[(w * 8 + 2*q + 1) * F + lane] = v.y;
    }
}

// ---------------------------------------------------------------------------
// Kernel 1b: reduce 32 partials -> M, then M2 = (M @ w_r) * invN
// One block per batch, 256 threads.
// ---------------------------------------------------------------------------
__global__ __launch_bounds__(256) void k_reduceM(const float* __restrict__ w_r)
{
    __shared__ float Ms[F * F];
    __shared__ float wrs[F * F];
    const int b = blockIdx.x;
    const int t = threadIdx.x;

#pragma unroll
    for (int e = t; e < F * F; e += 256) {
        float s = 0.0f;
        const float* mp = g_Mpart + (size_t)b * SPLITS * F * F + e;
#pragma unroll
        for (int sp = 0; sp < SPLITS; sp++) s += mp[sp * F * F];
        Ms[e] = s;
        wrs[e] = w_r[e];
    }
    __syncthreads();

    // M2[k][f] = invN * sum_m Ms[k][m] * w_r[m][f]; thread -> (k, 4 f's)
    const int k  = t >> 3;
    const int f0 = (t & 7) * 4;
    float a0 = 0.f, a1 = 0.f, a2 = 0.f, a3 = 0.f;
#pragma unroll
    for (int m = 0; m < F; m++) {
        const float mv = Ms[k * F + m];
        float4 w4 = *(const float4*)(wrs + m * F + f0);
        a0 += mv * w4.x; a1 += mv * w4.y; a2 += mv * w4.z; a3 += mv * w4.w;
    }
    float4* o4 = (float4*)(g_M2 + (size_t)b * F * F + k * F + f0);
    *o4 = make_float4(a0 * INV_N, a1 * INV_N, a2 * INV_N, a3 * INV_N);
}

// ---------------------------------------------------------------------------
// Kernel 2: out_i = x_i + psi_i @ M2 - (diag_i*invN) * (u_i @ w_r)
// 256 threads, 64 rows (4 threads/row, 8 features each).
// ---------------------------------------------------------------------------
// pool offsets (floats)
#define O_WPSI 0
#define O_WPHI 1024
#define O_WU   2048
#define O_WR   3072
#define O_M2   4096
#define O_BPSI 5120
#define O_BPHI 5152
#define O_BU   5184
#define O_XS   5216          // x tile, stride 33 (2112 used, 2176 reserved)
#define O_DIAG 7392          // 256 floats
#define POOL_F 7648
// aliases (valid after sync #0)
#define O_PSIS 0             // psi tile, stride 34 (2176 <= 3072 dead weights)
#define O_US   5216          // u tile, stride 34 (over dead x tile region)

__global__ __launch_bounds__(256) void k_main(
    const float* __restrict__ x,
    const float* __restrict__ w_psi, const float* __restrict__ b_psi,
    const float* __restrict__ w_phi, const float* __restrict__ b_phi,
    const float* __restrict__ w_u,   const float* __restrict__ b_u,
    const float* __restrict__ w_r,
    float* __restrict__ out)
{
    __shared__ alignas(16) float pool[POOL_F];

    const int b     = blockIdx.x >> 5;
    const int chunk = blockIdx.x & 31;
    const int t     = threadIdx.x;
    const int q     = t >> 6;            // quarter: features [q*8, q*8+8)
    const int r     = t & 63;            // local row
    const int hoff  = q * 8;

    // ---- cooperative loads ----
    {
        int i = t;   // 256 float4 per array, one each
        ((float4*)(pool + O_WPSI))[i] = ((const float4*)w_psi)[i];
        ((float4*)(pool + O_WPHI))[i] = ((const float4*)w_phi)[i];
        ((float4*)(pool + O_WU  ))[i] = ((const float4*)w_u  )[i];
        ((float4*)(pool + O_WR  ))[i] = ((const float4*)w_r  )[i];
        ((float4*)(pool + O_M2  ))[i] = ((const float4*)(g_M2 + (size_t)b * F * F))[i];
    }
    if (t < F) {
        pool[O_BPSI + t] = b_psi[t];
        pool[O_BPHI + t] = b_phi[t];
        pool[O_BU   + t] = b_u[t];
    }
    {
        const float* xg = x + ((size_t)b * NSEQ + chunk * 64) * F;
#pragma unroll
        for (int i = t; i < 512; i += 256) {
            int row = i >> 3, c = (i & 7) << 2;
            float4 v = ((const float4*)xg)[i];
            pool[O_XS + row * 33 + c + 0] = v.x;
            pool[O_XS + row * 33 + c + 1] = v.y;
            pool[O_XS + row * 33 + c + 2] = v.z;
            pool[O_XS + row * 33 + c + 3] = v.w;
        }
    }
    __syncthreads();

    // ---- loop1: psi/phi/u 8-feature slices (packed) ----
    u64 ps[4], ph[4], uv[4];
#pragma unroll
    for (int i = 0; i < 4; i++) {
        ps[i] = ((const u64*)(pool + O_BPSI))[q * 4 + i];
        ph[i] = ((const u64*)(pool + O_BPHI))[q * 4 + i];
        uv[i] = ((const u64*)(pool + O_BU  ))[q * 4 + i];
    }
#pragma unroll
    for (int k = 0; k < F; k++) {
        const float xk = pool[O_XS + r * 33 + k];
        const u64 xk2 = pk2(xk, xk);
        const ulonglong2* wp = (const ulonglong2*)(pool + O_WPSI + k * F + hoff);
        const ulonglong2* wf = (const ulonglong2*)(pool + O_WPHI + k * F + hoff);
        const ulonglong2* wu = (const ulonglong2*)(pool + O_WU   + k * F + hoff);
        {
            ulonglong2 a = wp[0], c = wp[1];
            ps[0] = ffma2(xk2, a.x, ps[0]); ps[1] = ffma2(xk2, a.y, ps[1]);
            ps[2] = ffma2(xk2, c.x, ps[2]); ps[3] = ffma2(xk2, c.y, ps[3]);
        }
        {
            ulonglong2 a = wf[0], c = wf[1];
            ph[0] = ffma2(xk2, a.x, ph[0]); ph[1] = ffma2(xk2, a.y, ph[1]);
            ph[2] = ffma2(xk2, c.x, ph[2]); ph[3] = ffma2(xk2, c.y, ph[3]);
        }
        {
            ulonglong2 a = wu[0], c = wu[1];
            uv[0] = ffma2(xk2, a.x, uv[0]); uv[1] = ffma2(xk2, a.y, uv[1]);
            uv[2] = ffma2(xk2, c.x, uv[2]); uv[3] = ffma2(xk2, c.y, uv[3]);
        }
    }
    // relu + partial diag
    u64 dac = 0ull;
#pragma unroll
    for (int i = 0; i < 4; i++) {
        float2 tu = up2(uv[i]);
        uv[i] = pk2(fmaxf(tu.x, 0.0f), fmaxf(tu.y, 0.0f));
        dac = ffma2(ps[i], ph[i], dac);
    }
    float2 dd = up2(dac);
    const float dpart = dd.x + dd.y;

    __syncthreads();   // #0: weight + x_s reads complete

    // stage psi (over dead weights), u (over dead x tile), diag partial
    u64* prow = (u64*)(pool + O_PSIS + r * 34 + hoff);
    u64* urow = (u64*)(pool + O_US   + r * 34 + hoff);
#pragma unroll
    for (int i = 0; i < 4; i++) { prow[i] = ps[i]; urow[i] = uv[i]; }
    pool[O_DIAG + r * 4 + q] = dpart;
    __syncthreads();   // #1

    const float diag = pool[O_DIAG + r * 4 + 0] + pool[O_DIAG + r * 4 + 1]
                     + pool[O_DIAG + r * 4 + 2] + pool[O_DIAG + r * 4 + 3];
    const float s = diag * INV_N;

    // ---- loop2: att2 = psi @ M2 ; uw = u @ w_r ----
    u64 at[4] = {0ull, 0ull, 0ull, 0ull};
    u64 uw[4] = {0ull, 0ull, 0ull, 0ull};
#pragma unroll
    for (int k = 0; k < F; k++) {
        const float pkv = pool[O_PSIS + r * 34 + k];
        const float ukv = pool[O_US   + r * 34 + k];
        const u64 pk2v = pk2(pkv, pkv);
        const u64 uk2v = pk2(ukv, ukv);
        const ulonglong2* mm = (const ulonglong2*)(pool + O_M2 + k * F + hoff);
        const ulonglong2* wr = (const ulonglong2*)(pool + O_WR + k * F + hoff);
        {
            ulonglong2 a = mm[0], c = mm[1];
            at[0] = ffma2(pk2v, a.x, at[0]); at[1] = ffma2(pk2v, a.y, at[1]);
            at[2] = ffma2(pk2v, c.x, at[2]); at[3] = ffma2(pk2v, c.y, at[3]);
        }
        {
            ulonglong2 a = wr[0], c = wr[1];
            uw[0] = ffma2(uk2v, a.x, uw[0]); uw[1] = ffma2(uk2v, a.y, uw[1]);
            uw[2] = ffma2(uk2v, c.x, uw[2]); uw[3] = ffma2(uk2v, c.y, uw[3]);
        }
    }

    // ---- out = x + att2 - s*uw ----
    const size_t g = ((size_t)b * NSEQ + chunk * 64 + r) * F + hoff;
    const u64 ns2 = pk2(-s, -s);
    float4 x0 = ((const float4*)(x + g))[0];
    float4 x1 = ((const float4*)(x + g))[1];
    u64 o0 = add2(ffma2(ns2, uw[0], at[0]), pk2(x0.x, x0.y));
    u64 o1 = add2(ffma2(ns2, uw[1], at[1]), pk2(x0.z, x0.w));
    u64 o2 = add2(ffma2(ns2, uw[2], at[2]), pk2(x1.x, x1.y));
    u64 o3 = add2(ffma2(ns2, uw[3], at[3]), pk2(x1.z, x1.w));
    float2 a0 = up2(o0), a1 = up2(o1), a2 = up2(o2), a3 = up2(o3);
    ((float4*)(out + g))[0] = make_float4(a0.x, a0.y, a1.x, a1.y);
    ((float4*)(out + g))[1] = make_float4(a2.x, a2.y, a3.x, a3.y);
}

// ---------------------------------------------------------------------------
extern "C" void kernel_launch(void* const* d_in, const int* in_sizes, int n_in,
                              void* d_out, int out_size)
{
    const float* x     = (const float*)d_in[0];
    const float* w_psi = (const float*)d_in[1];
    const float* b_psi = (const float*)d_in[2];
    const float* w_phi = (const float*)d_in[3];
    const float* b_phi = (const float*)d_in[4];
    const float* w_u   = (const float*)d_in[5];
    const float* b_u   = (const float*)d_in[6];
    const float* w_r   = (const float*)d_in[7];
    float* out = (float*)d_out;

    dim3 g1(BATCH, SPLITS);
    k_partialM<<<g1, 128>>>(x, w_phi, b_phi, w_u, b_u);
    k_reduceM<<<BATCH, 256>>>(w_r);
    k_main<<<BATCH * 32, 256>>>(x, w_psi, b_psi, w_phi, b_phi,
                                w_u, b_u, w_r, out);
}

// round 8
// speedup vs baseline: 1.0419x; 1.0419x over previous
#include <cuda_runtime.h>

typedef unsigned long long u64;

#define BATCH 32
#define NSEQ  2048
#define F     32
#define SPLITS 32
#define ROWS1 64                // rows per kernel-1 block
#define INV_N (1.0f / 2048.0f)

// Scratch (fully overwritten every launch -> deterministic)
__device__ float g_Mpart[BATCH * SPLITS * F * F];
__device__ float g_M2[BATCH * F * F];               // (M @ w_r) * invN

// ---- packed f32x2 helpers ----
__device__ __forceinline__ u64 pk2(float a, float b) {
    u64 r; asm("mov.b64 %0,{%1,%2};" : "=l"(r) : "f"(a), "f"(b)); return r;
}
__device__ __forceinline__ float2 up2(u64 v) {
    float2 f; asm("mov.b64 {%0,%1},%2;" : "=f"(f.x), "=f"(f.y) : "l"(v)); return f;
}
__device__ __forceinline__ u64 ffma2(u64 a, u64 b, u64 c) {
    u64 d; asm("fma.rn.f32x2 %0,%1,%2,%3;" : "=l"(d) : "l"(a), "l"(b), "l"(c)); return d;
}
__device__ __forceinline__ u64 add2(u64 a, u64 b) {
    u64 d; asm("add.rn.f32x2 %0,%1,%2;" : "=l"(d) : "l"(a), "l"(b)); return d;
}

// ---------------------------------------------------------------------------
// Kernel 1: partial M_b[f1][f2] = sum_j phi[j][f1]*u[j][f2] over 64-row slice.
// 128 threads. Phase A: 2 threads/row. Phase B: LDS.128 phi loads (stride 36).
// ---------------------------------------------------------------------------
__global__ __launch_bounds__(128) void k_partialM(
    const float* __restrict__ x,
    const float* __restrict__ w_phi, const float* __restrict__ b_phi,
    const float* __restrict__ w_u,   const float* __restrict__ b_u)
{
    __shared__ alignas(16) float ws_phi[F * F], ws_u[F * F];
    __shared__ alignas(16) float bs_phi[F], bs_u[F];
    __shared__ alignas(16) float phi_s[ROWS1 * 36];   // [j][f], stride 36 (16B-aligned)
    __shared__ alignas(16) float u_s[ROWS1 * 36];

    const int b     = blockIdx.x;
    const int split = blockIdx.y;
    const int t     = threadIdx.x;

#pragma unroll
    for (int i = t; i < 256; i += 128) {
        ((float4*)ws_phi)[i] = ((const float4*)w_phi)[i];
        ((float4*)ws_u  )[i] = ((const float4*)w_u  )[i];
    }
    if (t < F) { bs_phi[t] = b_phi[t]; bs_u[t] = b_u[t]; }
    __syncthreads();

    // ---- Phase A: row r = t&63, half h = t>>6 -> features [h*16, h*16+16)
    const int r    = t & 63;
    const int h    = t >> 6;
    const int hoff = h * 16;
    const int row  = split * ROWS1 + r;

    const float4* xr = (const float4*)(x + ((size_t)b * NSEQ + row) * F);
    float xv[F];
#pragma unroll
    for (int i = 0; i < 8; i++) {
        float4 v = xr[i];
        xv[4*i+0] = v.x; xv[4*i+1] = v.y; xv[4*i+2] = v.z; xv[4*i+3] = v.w;
    }

    u64 ph[8], uv[8];
#pragma unroll
    for (int i = 0; i < 8; i++) {
        ph[i] = ((const u64*)bs_phi)[h * 8 + i];
        uv[i] = ((const u64*)bs_u  )[h * 8 + i];
    }
#pragma unroll
    for (int k = 0; k < F; k++) {
        const u64 xk2 = pk2(xv[k], xv[k]);
        const ulonglong2* wp = (const ulonglong2*)(ws_phi + k * F + hoff);
        const ulonglong2* wu = (const ulonglong2*)(ws_u   + k * F + hoff);
#pragma unroll
        for (int q = 0; q < 4; q++) {
            ulonglong2 a = wp[q];
            ph[2*q+0] = ffma2(xk2, a.x, ph[2*q+0]);
            ph[2*q+1] = ffma2(xk2, a.y, ph[2*q+1]);
        }
#pragma unroll
        for (int q = 0; q < 4; q++) {
            ulonglong2 a = wu[q];
            uv[2*q+0] = ffma2(xk2, a.x, uv[2*q+0]);
            uv[2*q+1] = ffma2(xk2, a.y, uv[2*q+1]);
        }
    }
    u64* prow = (u64*)(phi_s + r * 36 + hoff);
    u64* urow = (u64*)(u_s   + r * 36 + hoff);
#pragma unroll
    for (int i = 0; i < 8; i++) {
        prow[i] = ph[i];
        float2 tu = up2(uv[i]);
        urow[i] = pk2(fmaxf(tu.x, 0.0f), fmaxf(tu.y, 0.0f));
    }
    __syncthreads();

    // ---- Phase B: warp w owns f1 in [8w,8w+8), lane = f2.
    // Per j: 1 lane-strided LDS (u) + 2 uniform LDS.128 (phi) + 4 FFMA2.
    const int lane = t & 31;
    const int w    = t >> 5;
    u64 acc2[4] = {0ull, 0ull, 0ull, 0ull};

#pragma unroll 4
    for (int j = 0; j < ROWS1; j++) {
        const float uj = u_s[j * 36 + lane];               // conflict-free
        const u64 uj2 = pk2(uj, uj);
        const ulonglong2* pr = (const ulonglong2*)(phi_s + j * 36 + w * 8);
        ulonglong2 p0 = pr[0], p1 = pr[1];                 // 2x LDS.128 broadcast
        acc2[0] = ffma2(uj2, p0.x, acc2[0]);
        acc2[1] = ffma2(uj2, p0.y, acc2[1]);
        acc2[2] = ffma2(uj2, p1.x, acc2[2]);
        acc2[3] = ffma2(uj2, p1.y, acc2[3]);
    }

    float* mp = g_Mpart + ((size_t)(b * SPLITS + split)) * F * F;
#pragma unroll
    for (int q = 0; q < 4; q++) {
        float2 v = up2(acc2[q]);
        mp[(w * 8 + 2*q + 0) * F + lane] = v.x;
        mp[(w * 8 + 2*q + 1) * F + lane] = v.y;
    }
}

// ---------------------------------------------------------------------------
// Kernel 1b: reduce 32 partials -> M, then M2 = (M @ w_r) * invN
// ---------------------------------------------------------------------------
__global__ __launch_bounds__(256) void k_reduceM(const float* __restrict__ w_r)
{
    __shared__ float Ms[F * F];
    __shared__ float wrs[F * F];
    const int b = blockIdx.x;
    const int t = threadIdx.x;

#pragma unroll
    for (int e = t; e < F * F; e += 256) {
        float s = 0.0f;
        const float* mp = g_Mpart + (size_t)b * SPLITS * F * F + e;
#pragma unroll
        for (int sp = 0; sp < SPLITS; sp++) s += mp[sp * F * F];
        Ms[e] = s;
        wrs[e] = w_r[e];
    }
    __syncthreads();

    const int k  = t >> 3;
    const int f0 = (t & 7) * 4;
    float a0 = 0.f, a1 = 0.f, a2 = 0.f, a3 = 0.f;
#pragma unroll
    for (int m = 0; m < F; m++) {
        const float mv = Ms[k * F + m];
        float4 w4 = *(const float4*)(wrs + m * F + f0);
        a0 += mv * w4.x; a1 += mv * w4.y; a2 += mv * w4.z; a3 += mv * w4.w;
    }
    float4* o4 = (float4*)(g_M2 + (size_t)b * F * F + k * F + f0);
    *o4 = make_float4(a0 * INV_N, a1 * INV_N, a2 * INV_N, a3 * INV_N);
}

// ---------------------------------------------------------------------------
// Kernel 2: out_i = x_i + psi_i @ M2 - (diag_i*invN) * (u_i @ w_r)
// 128 threads, 64 rows (2 threads/row, 16 features each).
// ---------------------------------------------------------------------------
// pool offsets (floats)
#define O_WPSI 0
#define O_WPHI 1024
#define O_WU   2048
#define O_WR   3072
#define O_M2   4096
#define O_BPSI 5120
#define O_BPHI 5152
#define O_BU   5184
#define O_XS   5216          // x tile, stride 33 (2112 floats)
#define POOL_F 7520
// aliases (valid after sync #0: w_psi/w_phi/w_u and x tile are dead)
#define O_PSIS 0             // psi tile, stride 36: 2304 floats < 3072 (w_r live at 3072)
#define O_DIAG 2304          // 128 floats, ends 2432 < 3072
#define O_US   5216          // u tile, stride 36: 5216+2304 = 7520 = POOL_F

__global__ __launch_bounds__(128) void k_main(
    const float* __restrict__ x,
    const float* __restrict__ w_psi, const float* __restrict__ b_psi,
    const float* __restrict__ w_phi, const float* __restrict__ b_phi,
    const float* __restrict__ w_u,   const float* __restrict__ b_u,
    const float* __restrict__ w_r,
    float* __restrict__ out)
{
    __shared__ alignas(16) float pool[POOL_F];

    const int b     = blockIdx.x >> 5;
    const int chunk = blockIdx.x & 31;
    const int t     = threadIdx.x;
    const int half  = t >> 6;            // features [half*16, half*16+16)
    const int r     = t & 63;
    const int hoff  = half * 16;

    // ---- cooperative loads ----
#pragma unroll
    for (int i = t; i < 256; i += 128) {
        ((float4*)(pool + O_WPSI))[i] = ((const float4*)w_psi)[i];
        ((float4*)(pool + O_WPHI))[i] = ((const float4*)w_phi)[i];
        ((float4*)(pool + O_WU  ))[i] = ((const float4*)w_u  )[i];
        ((float4*)(pool + O_WR  ))[i] = ((const float4*)w_r  )[i];
        ((float4*)(pool + O_M2  ))[i] = ((const float4*)(g_M2 + (size_t)b * F * F))[i];
    }
    if (t < F) {
        pool[O_BPSI + t] = b_psi[t];
        pool[O_BPHI + t] = b_phi[t];
        pool[O_BU   + t] = b_u[t];
    }
    {
        const float* xg = x + ((size_t)b * NSEQ + chunk * 64) * F;
#pragma unroll
        for (int i = t; i < 512; i += 128) {
            int row = i >> 3, c = (i & 7) << 2;
            float4 v = ((const float4*)xg)[i];
            pool[O_XS + row * 33 + c + 0] = v.x;
            pool[O_XS + row * 33 + c + 1] = v.y;
            pool[O_XS + row * 33 + c + 2] = v.z;
            pool[O_XS + row * 33 + c + 3] = v.w;
        }
    }
    __syncthreads();

    // ---- loop1: psi/phi/u 16-feature halves (packed) ----
    u64 ps[8], ph[8], uv[8];
#pragma unroll
    for (int i = 0; i < 8; i++) {
        ps[i] = ((const u64*)(pool + O_BPSI))[half * 8 + i];
        ph[i] = ((const u64*)(pool + O_BPHI))[half * 8 + i];
        uv[i] = ((const u64*)(pool + O_BU  ))[half * 8 + i];
    }
#pragma unroll
    for (int k = 0; k < F; k++) {
        const float xk = pool[O_XS + r * 33 + k];
        const u64 xk2 = pk2(xk, xk);
        const ulonglong2* wp = (const ulonglong2*)(pool + O_WPSI + k * F + hoff);
        const ulonglong2* wf = (const ulonglong2*)(pool + O_WPHI + k * F + hoff);
        const ulonglong2* wu = (const ulonglong2*)(pool + O_WU   + k * F + hoff);
#pragma unroll
        for (int q = 0; q < 4; q++) {
            ulonglong2 a = wp[q];
            ps[2*q+0] = ffma2(xk2, a.x, ps[2*q+0]);
            ps[2*q+1] = ffma2(xk2, a.y, ps[2*q+1]);
        }
#pragma unroll
        for (int q = 0; q < 4; q++) {
            ulonglong2 a = wf[q];
            ph[2*q+0] = ffma2(xk2, a.x, ph[2*q+0]);
            ph[2*q+1] = ffma2(xk2, a.y, ph[2*q+1]);
        }
#pragma unroll
        for (int q = 0; q < 4; q++) {
            ulonglong2 a = wu[q];
            uv[2*q+0] = ffma2(xk2, a.x, uv[2*q+0]);
            uv[2*q+1] = ffma2(xk2, a.y, uv[2*q+1]);
        }
    }
    // relu + partial diag
    u64 dac = 0ull;
#pragma unroll
    for (int i = 0; i < 8; i++) {
        float2 tu = up2(uv[i]);
        uv[i] = pk2(fmaxf(tu.x, 0.0f), fmaxf(tu.y, 0.0f));
        dac = ffma2(ps[i], ph[i], dac);
    }
    float2 dd = up2(dac);
    const float dpart = dd.x + dd.y;

    __syncthreads();   // #0: weight psi/phi/u + x_s reads complete

    // stage psi, u (stride 36, 16B-aligned), diag partial
    u64* prow = (u64*)(pool + O_PSIS + r * 36 + hoff);
    u64* urow = (u64*)(pool + O_US   + r * 36 + hoff);
#pragma unroll
    for (int i = 0; i < 8; i++) { prow[i] = ps[i]; urow[i] = uv[i]; }
    pool[O_DIAG + r * 2 + half] = dpart;
    __syncthreads();   // #1

    const float diag = pool[O_DIAG + r * 2] + pool[O_DIAG + r * 2 + 1];
    const float s = diag * INV_N;

    // ---- loop2: at = psi @ M2 ; uw = u @ w_r (16 features each) ----
    u64 at[8] = {0,0,0,0,0,0,0,0};
    u64 uw[8] = {0,0,0,0,0,0,0,0};
#pragma unroll
    for (int k = 0; k < F; k++) {
        const float pkv = pool[O_PSIS + r * 36 + k];
        const float ukv = pool[O_US   + r * 36 + k];
        const u64 pk2v = pk2(pkv, pkv);
        const u64 uk2v = pk2(ukv, ukv);
        const ulonglong2* mm = (const ulonglong2*)(pool + O_M2 + k * F + hoff);
        const ulonglong2* wr = (const ulonglong2*)(pool + O_WR + k * F + hoff);
#pragma unroll
        for (int q = 0; q < 4; q++) {
            ulonglong2 a = mm[q];
            at[2*q+0] = ffma2(pk2v, a.x, at[2*q+0]);
            at[2*q+1] = ffma2(pk2v, a.y, at[2*q+1]);
        }
#pragma unroll
        for (int q = 0; q < 4; q++) {
            ulonglong2 a = wr[q];
            uw[2*q+0] = ffma2(uk2v, a.x, uw[2*q+0]);
            uw[2*q+1] = ffma2(uk2v, a.y, uw[2*q+1]);
        }
    }

    // ---- out = x + at - s*uw ----
    const size_t g = ((size_t)b * NSEQ + chunk * 64 + r) * F + hoff;
    const u64 ns2 = pk2(-s, -s);
#pragma unroll
    for (int q = 0; q < 4; q++) {
        float4 xq = ((const float4*)(x + g))[q];
        u64 o0 = add2(ffma2(ns2, uw[2*q+0], at[2*q+0]), pk2(xq.x, xq.y));
        u64 o1 = add2(ffma2(ns2, uw[2*q+1], at[2*q+1]), pk2(xq.z, xq.w));
        float2 a0 = up2(o0), a1 = up2(o1);
        ((float4*)(out + g))[q] = make_float4(a0.x, a0.y, a1.x, a1.y);
    }
}

// ---------------------------------------------------------------------------
extern "C" void kernel_launch(void* const* d_in, const int* in_sizes, int n_in,
                              void* d_out, int out_size)
{
    const float* x     = (const float*)d_in[0];
    const float* w_psi = (const float*)d_in[1];
    const float* b_psi = (const float*)d_in[2];
    const float* w_phi = (const float*)d_in[3];
    const float* b_phi = (const float*)d_in[4];
    const float* w_u   = (const float*)d_in[5];
    const float* b_u   = (const float*)d_in[6];
    const float* w_r   = (const float*)d_in[7];
    float* out = (float*)d_out;

    dim3 g1(BATCH, SPLITS);
    k_partialM<<<g1, 128>>>(x, w_phi, b_phi, w_u, b_u);
    k_reduceM<<<BATCH, 256>>>(w_r);
    k_main<<<BATCH * 32, 128>>>(x, w_psi, b_psi, w_phi, b_phi,
                                w_u, b_u, w_r, out);
}

// round 9
// speedup vs baseline: 1.0522x; 1.0099x over previous
#include <cuda_runtime.h>

typedef unsigned long long u64;

#define BATCH 32
#define NSEQ  2048
#define F     32
#define SPLITS 32
#define ROWS1 64
#define INV_N (1.0f / 2048.0f)

// Scratch (fully overwritten every launch -> deterministic)
__device__ float g_Mpart[BATCH * SPLITS * F * F];
__device__ float g_M2[BATCH * F * F];          // (M @ w_r) * invN
__device__ float g_psi[BATCH * NSEQ * F];      // 8 MB
__device__ float g_u[BATCH * NSEQ * F];        // 8 MB
__device__ float g_diag[BATCH * NSEQ];         // 256 KB

// ---- packed f32x2 helpers ----
__device__ __forceinline__ u64 pk2(float a, float b) {
    u64 r; asm("mov.b64 %0,{%1,%2};" : "=l"(r) : "f"(a), "f"(b)); return r;
}
__device__ __forceinline__ float2 up2(u64 v) {
    float2 f; asm("mov.b64 {%0,%1},%2;" : "=f"(f.x), "=f"(f.y) : "l"(v)); return f;
}
__device__ __forceinline__ u64 ffma2(u64 a, u64 b, u64 c) {
    u64 d; asm("fma.rn.f32x2 %0,%1,%2,%3;" : "=l"(d) : "l"(a), "l"(b), "l"(c)); return d;
}
__device__ __forceinline__ u64 add2(u64 a, u64 b) {
    u64 d; asm("add.rn.f32x2 %0,%1,%2;" : "=l"(d) : "l"(a), "l"(b)); return d;
}

// ---------------------------------------------------------------------------
// Kernel 1: per 64-row slice:
//   psi,phi,u (3 matvecs, 2 thr/row x 16 feats), diag, partial M.
//   Persists psi, u (relu'd), diag to global scratch.
// ---------------------------------------------------------------------------
__global__ __launch_bounds__(128) void k_partialM(
    const float* __restrict__ x,
    const float* __restrict__ w_psi, const float* __restrict__ b_psi,
    const float* __restrict__ w_phi, const float* __restrict__ b_phi,
    const float* __restrict__ w_u,   const float* __restrict__ b_u)
{
    __shared__ alignas(16) float ws_psi[F * F], ws_phi[F * F], ws_u[F * F];
    __shared__ alignas(16) float bs_psi[F], bs_phi[F], bs_u[F];
    __shared__ alignas(16) float phi_s[ROWS1 * 36];
    __shared__ alignas(16) float u_s[ROWS1 * 36];
    __shared__ float ds[2][ROWS1];

    const int b     = blockIdx.x;
    const int split = blockIdx.y;
    const int t     = threadIdx.x;

#pragma unroll
    for (int i = t; i < 256; i += 128) {
        ((float4*)ws_psi)[i] = ((const float4*)w_psi)[i];
        ((float4*)ws_phi)[i] = ((const float4*)w_phi)[i];
        ((float4*)ws_u  )[i] = ((const float4*)w_u  )[i];
    }
    if (t < F) { bs_psi[t] = b_psi[t]; bs_phi[t] = b_phi[t]; bs_u[t] = b_u[t]; }
    __syncthreads();

    // ---- Phase A: row r = t&63, half h = t>>6 -> features [h*16, h*16+16)
    const int r    = t & 63;
    const int h    = t >> 6;
    const int hoff = h * 16;
    const int row  = split * ROWS1 + r;
    const size_t grow = ((size_t)b * NSEQ + row) * F + hoff;

    const float4* xr = (const float4*)(x + ((size_t)b * NSEQ + row) * F);
    float xv[F];
#pragma unroll
    for (int i = 0; i < 8; i++) {
        float4 v = xr[i];
        xv[4*i+0] = v.x; xv[4*i+1] = v.y; xv[4*i+2] = v.z; xv[4*i+3] = v.w;
    }

    u64 ps[8], ph[8], uv[8];
#pragma unroll
    for (int i = 0; i < 8; i++) {
        ps[i] = ((const u64*)bs_psi)[h * 8 + i];
        ph[i] = ((const u64*)bs_phi)[h * 8 + i];
        uv[i] = ((const u64*)bs_u  )[h * 8 + i];
    }
#pragma unroll
    for (int k = 0; k < F; k++) {
        const u64 xk2 = pk2(xv[k], xv[k]);
        const ulonglong2* wp = (const ulonglong2*)(ws_psi + k * F + hoff);
        const ulonglong2* wf = (const ulonglong2*)(ws_phi + k * F + hoff);
        const ulonglong2* wu = (const ulonglong2*)(ws_u   + k * F + hoff);
#pragma unroll
        for (int q = 0; q < 4; q++) {
            ulonglong2 a = wp[q];
            ps[2*q+0] = ffma2(xk2, a.x, ps[2*q+0]);
            ps[2*q+1] = ffma2(xk2, a.y, ps[2*q+1]);
        }
#pragma unroll
        for (int q = 0; q < 4; q++) {
            ulonglong2 a = wf[q];
            ph[2*q+0] = ffma2(xk2, a.x, ph[2*q+0]);
            ph[2*q+1] = ffma2(xk2, a.y, ph[2*q+1]);
        }
#pragma unroll
        for (int q = 0; q < 4; q++) {
            ulonglong2 a = wu[q];
            uv[2*q+0] = ffma2(xk2, a.x, uv[2*q+0]);
            uv[2*q+1] = ffma2(xk2, a.y, uv[2*q+1]);
        }
    }

    // relu + diag partial
    u64 dac = 0ull;
#pragma unroll
    for (int i = 0; i < 8; i++) {
        float2 tu = up2(uv[i]);
        uv[i] = pk2(fmaxf(tu.x, 0.0f), fmaxf(tu.y, 0.0f));
        dac = ffma2(ps[i], ph[i], dac);
    }
    float2 dd = up2(dac);
    ds[h][r] = dd.x + dd.y;

    // persist psi, u (STG.128 x4 each, contiguous 64B per thread)
#pragma unroll
    for (int q = 0; q < 4; q++) {
        float2 p0 = up2(ps[2*q+0]), p1 = up2(ps[2*q+1]);
        ((float4*)(g_psi + grow))[q] = make_float4(p0.x, p0.y, p1.x, p1.y);
        float2 v0 = up2(uv[2*q+0]), v1 = up2(uv[2*q+1]);
        ((float4*)(g_u + grow))[q]   = make_float4(v0.x, v0.y, v1.x, v1.y);
    }

    // stage phi, u for phase B
    u64* prow = (u64*)(phi_s + r * 36 + hoff);
    u64* urow = (u64*)(u_s   + r * 36 + hoff);
#pragma unroll
    for (int i = 0; i < 8; i++) { prow[i] = ph[i]; urow[i] = uv[i]; }
    __syncthreads();

    if (t < ROWS1)
        g_diag[(size_t)b * NSEQ + split * ROWS1 + t] = ds[0][t] + ds[1][t];

    // ---- Phase B: warp w owns f1 in [8w,8w+8), lane = f2.
    const int lane = t & 31;
    const int w    = t >> 5;
    u64 acc2[4] = {0ull, 0ull, 0ull, 0ull};

#pragma unroll 4
    for (int j = 0; j < ROWS1; j++) {
        const float uj = u_s[j * 36 + lane];
        const u64 uj2 = pk2(uj, uj);
        const ulonglong2* pr = (const ulonglong2*)(phi_s + j * 36 + w * 8);
        ulonglong2 p0 = pr[0], p1 = pr[1];
        acc2[0] = ffma2(uj2, p0.x, acc2[0]);
        acc2[1] = ffma2(uj2, p0.y, acc2[1]);
        acc2[2] = ffma2(uj2, p1.x, acc2[2]);
        acc2[3] = ffma2(uj2, p1.y, acc2[3]);
    }

    float* mp = g_Mpart + ((size_t)(b * SPLITS + split)) * F * F;
#pragma unroll
    for (int q = 0; q < 4; q++) {
        float2 v = up2(acc2[q]);
        mp[(w * 8 + 2*q + 0) * F + lane] = v.x;
        mp[(w * 8 + 2*q + 1) * F + lane] = v.y;
    }
}

// ---------------------------------------------------------------------------
// Kernel 1b: reduce 32 partials -> M, then M2 = (M @ w_r) * invN
// ---------------------------------------------------------------------------
__global__ __launch_bounds__(256) void k_reduceM(const float* __restrict__ w_r)
{
    __shared__ float Ms[F * F];
    __shared__ float wrs[F * F];
    const int b = blockIdx.x;
    const int t = threadIdx.x;

#pragma unroll
    for (int e = t; e < F * F; e += 256) {
        float s = 0.0f;
        const float* mp = g_Mpart + (size_t)b * SPLITS * F * F + e;
#pragma unroll
        for (int sp = 0; sp < SPLITS; sp++) s += mp[sp * F * F];
        Ms[e] = s;
        wrs[e] = w_r[e];
    }
    __syncthreads();

    const int k  = t >> 3;
    const int f0 = (t & 7) * 4;
    float a0 = 0.f, a1 = 0.f, a2 = 0.f, a3 = 0.f;
#pragma unroll
    for (int m = 0; m < F; m++) {
        const float mv = Ms[k * F + m];
        float4 w4 = *(const float4*)(wrs + m * F + f0);
        a0 += mv * w4.x; a1 += mv * w4.y; a2 += mv * w4.z; a3 += mv * w4.w;
    }
    float4* o4 = (float4*)(g_M2 + (size_t)b * F * F + k * F + f0);
    *o4 = make_float4(a0 * INV_N, a1 * INV_N, a2 * INV_N, a3 * INV_N);
}

// ---------------------------------------------------------------------------
// Kernel 2 (light): out = x + psi @ M2 - (diag*invN) * (u @ w_r)
// 128 threads, 64 rows (2 thr/row, 16 feats). psi/u/diag from scratch.
// ---------------------------------------------------------------------------
__global__ __launch_bounds__(128) void k_main(
    const float* __restrict__ x,
    const float* __restrict__ w_r,
    float* __restrict__ out)
{
    __shared__ alignas(16) float wrs[F * F];
    __shared__ alignas(16) float m2s[F * F];
    __shared__ alignas(16) float psi_s[ROWS1 * 36];
    __shared__ alignas(16) float u_s[ROWS1 * 36];
    __shared__ float dia_s[ROWS1];

    const int b     = blockIdx.x >> 5;
    const int chunk = blockIdx.x & 31;
    const int t     = threadIdx.x;
    const int half  = t >> 6;
    const int r     = t & 63;
    const int hoff  = half * 16;
    const size_t rowbase = (size_t)b * NSEQ + chunk * 64;

#pragma unroll
    for (int i = t; i < 256; i += 128) {
        ((float4*)wrs)[i] = ((const float4*)w_r)[i];
        ((float4*)m2s)[i] = ((const float4*)(g_M2 + (size_t)b * F * F))[i];
    }
    // stage psi, u tiles (coalesced LDG -> smem stride 36)
#pragma unroll
    for (int i = t; i < 512; i += 128) {
        int row = i >> 3, c = (i & 7) << 2;
        float4 p = ((const float4*)(g_psi + rowbase * F))[i];
        float4 v = ((const float4*)(g_u   + rowbase * F))[i];
        *(float4*)(psi_s + row * 36 + c) = p;
        *(float4*)(u_s   + row * 36 + c) = v;
    }
    if (t < ROWS1) dia_s[t] = g_diag[rowbase + t];
    __syncthreads();

    // ---- at = psi @ M2 ; uw = u @ w_r (16 features each) ----
    u64 at[8] = {0,0,0,0,0,0,0,0};
    u64 uw[8] = {0,0,0,0,0,0,0,0};
#pragma unroll
    for (int k = 0; k < F; k++) {
        const float pkv = psi_s[r * 36 + k];
        const float ukv = u_s  [r * 36 + k];
        const u64 pk2v = pk2(pkv, pkv);
        const u64 uk2v = pk2(ukv, ukv);
        const ulonglong2* mm = (const ulonglong2*)(m2s + k * F + hoff);
        const ulonglong2* wr = (const ulonglong2*)(wrs + k * F + hoff);
#pragma unroll
        for (int q = 0; q < 4; q++) {
            ulonglong2 a = mm[q];
            at[2*q+0] = ffma2(pk2v, a.x, at[2*q+0]);
            at[2*q+1] = ffma2(pk2v, a.y, at[2*q+1]);
        }
#pragma unroll
        for (int q = 0; q < 4; q++) {
            ulonglong2 a = wr[q];
            uw[2*q+0] = ffma2(uk2v, a.x, uw[2*q+0]);
            uw[2*q+1] = ffma2(uk2v, a.y, uw[2*q+1]);
        }
    }

    // ---- out = x + at - s*uw ----
    const float s = dia_s[r] * INV_N;
    const size_t g = (rowbase + r) * F + hoff;
    const u64 ns2 = pk2(-s, -s);
#pragma unroll
    for (int q = 0; q < 4; q++) {
        float4 xq = ((const float4*)(x + g))[q];
        u64 o0 = add2(ffma2(ns2, uw[2*q+0], at[2*q+0]), pk2(xq.x, xq.y));
        u64 o1 = add2(ffma2(ns2, uw[2*q+1], at[2*q+1]), pk2(xq.z, xq.w));
        float2 a0 = up2(o0), a1 = up2(o1);
        ((float4*)(out + g))[q] = make_float4(a0.x, a0.y, a1.x, a1.y);
    }
}

// ---------------------------------------------------------------------------
extern "C" void kernel_launch(void* const* d_in, const int* in_sizes, int n_in,
                              void* d_out, int out_size)
{
    const float* x     = (const float*)d_in[0];
    const float* w_psi = (const float*)d_in[1];
    const float* b_psi = (const float*)d_in[2];
    const float* w_phi = (const float*)d_in[3];
    const float* b_phi = (const float*)d_in[4];
    const float* w_u   = (const float*)d_in[5];
    const float* b_u   = (const float*)d_in[6];
    const float* w_r   = (const float*)d_in[7];
    float* out = (float*)d_out;

    dim3 g1(BATCH, SPLITS);
    k_partialM<<<g1, 128>>>(x, w_psi, b_psi, w_phi, b_phi, w_u, b_u);
    k_reduceM<<<BATCH, 256>>>(w_r);
    k_main<<<BATCH * 32, 128>>>(x, w_r, out);
}